// round 4
// baseline (speedup 1.0000x reference)
#include <cuda_runtime.h>

#define NN 1024
#define BN 4096
#define NH 8
#define TI 16
#define TJ 32

typedef unsigned long long ull;

// ---- scratch ----
__device__ float g_V[BN*128];
__device__ float g_SKIP[BN*128];
__device__ float g_A1[BN*NH];
__device__ float g_A2[BN*NH];
__device__ float g_ATTG[4*NH];

// ---- packed f32x2 helpers ----
__device__ __forceinline__ ull ffma2(ull a, ull b, ull c) {
    ull d; asm("fma.rn.f32x2 %0,%1,%2,%3;" : "=l"(d) : "l"(a), "l"(b), "l"(c)); return d;
}
__device__ __forceinline__ ull fadd2(ull a, ull b) {
    ull d; asm("add.rn.f32x2 %0,%1,%2;" : "=l"(d) : "l"(a), "l"(b)); return d;
}
__device__ __forceinline__ ull fmul2(ull a, ull b) {
    ull d; asm("mul.rn.f32x2 %0,%1,%2;" : "=l"(d) : "l"(a), "l"(b)); return d;
}
__device__ __forceinline__ ull pack2(float x, float y) {
    ull r; asm("mov.b64 %0,{%1,%2};" : "=l"(r) : "f"(x), "f"(y)); return r;
}
__device__ __forceinline__ float2 unpack2(ull v) {
    float2 r; asm("mov.b64 {%0,%1},%2;" : "=f"(r.x), "=f"(r.y) : "l"(v)); return r;
}
__device__ __forceinline__ ull shflx2(ull v, int m) {
    unsigned lo = (unsigned)v, hi = (unsigned)(v >> 32);
    lo = __shfl_xor_sync(0xffffffffu, lo, m);
    hi = __shfl_xor_sync(0xffffffffu, hi, m);
    return ((ull)hi << 32) | (ull)lo;
}

// =====================================================================
// Kernel A: per-node GEMMs. 16 rows/block (grid 256, 3 blocks/SM).
// thread = 2 rows x 4 cols. attg folded into block 0.
// =====================================================================
#define ZSTR 260
__global__ __launch_bounds__(256, 3) void gat_prep(
    const float* __restrict__ node, const float* __restrict__ hidden,
    const float* __restrict__ m_w,  const float* __restrict__ m_b,
    const float* __restrict__ skip_w, const float* __restrict__ skip_b,
    const float* __restrict__ a1_w, const float* __restrict__ a1_b,
    const float* __restrict__ a2_w, const float* __restrict__ a2_b,
    const float* __restrict__ graph, const float* __restrict__ ag_w,
    const float* __restrict__ ag_b)
{
    extern __shared__ float sm[];
    float* zs = sm;              // 16 * ZSTR
    float* ws = sm + 16*ZSTR;    // 8192 floats

    const int tid = threadIdx.x;
    const int r0  = blockIdx.x * 16;

    for (int t = tid; t < 16*64; t += 256) {
        int r = t >> 6, q = t & 63;
        float4 v = (q < 32) ? ((const float4*)node)[(r0 + r)*32 + q]
                            : ((const float4*)hidden)[(r0 + r)*32 + (q - 32)];
        *(float4*)&zs[r*ZSTR + q*4] = v;
    }

    const int cg = tid & 31;
    const int rg = tid >> 5;
    const int c0 = cg * 4;
    const int rowb = rg * 2;

    ull av[2][2], ak[2][2];
    {
        ulonglong2 bv = *(const ulonglong2*)&m_b[c0];
        ulonglong2 bk = *(const ulonglong2*)&skip_b[c0];
        #pragma unroll
        for (int rr = 0; rr < 2; ++rr) {
            av[rr][0] = bv.x; av[rr][1] = bv.y;
            ak[rr][0] = bk.x; ak[rr][1] = bk.y;
        }
    }

    for (int kk = 0; kk < 256; kk += 32) {
        __syncthreads();
        for (int t = tid; t < 2048; t += 256) {
            float4 v = (t < 1024) ? ((const float4*)m_w)[kk*32 + t]
                                  : ((const float4*)skip_w)[kk*32 + (t - 1024)];
            ((float4*)ws)[t] = v;
        }
        __syncthreads();
        #pragma unroll
        for (int k = 0; k < 32; ++k) {
            ulonglong2 wv = *(const ulonglong2*)&ws[k*128 + c0];
            ulonglong2 wk = *(const ulonglong2*)&ws[4096 + k*128 + c0];
            #pragma unroll
            for (int rr = 0; rr < 2; ++rr) {
                float z = zs[(rowb + rr)*ZSTR + kk + k];
                ull zz = pack2(z, z);
                av[rr][0] = ffma2(zz, wv.x, av[rr][0]);
                av[rr][1] = ffma2(zz, wv.y, av[rr][1]);
                ak[rr][0] = ffma2(zz, wk.x, ak[rr][0]);
                ak[rr][1] = ffma2(zz, wk.y, ak[rr][1]);
            }
        }
    }
    #pragma unroll
    for (int rr = 0; rr < 2; ++rr) {
        int rowg = r0 + rowb + rr;
        ulonglong2 o;
        o.x = av[rr][0]; o.y = av[rr][1];
        *(ulonglong2*)&g_V[rowg*128 + c0] = o;
        o.x = ak[rr][0]; o.y = ak[rr][1];
        *(ulonglong2*)&g_SKIP[rowg*128 + c0] = o;
    }

    // ---- att1 / att2 tail + attg ----
    __syncthreads();
    for (int t = tid; t < 2048; t += 256) {
        ws[t] = a1_w[t];
        ws[4096 + t] = a2_w[t];
    }
    __syncthreads();
    if (tid < 128) {
        int row = tid >> 3, h = tid & 7;
        float a1a = a1_b[h], a1c = 0.0f, a2a = a2_b[h], a2c = 0.0f;
        const float* zp = &zs[row*ZSTR];
        #pragma unroll 8
        for (int k = 0; k < 128; ++k) {
            float za = zp[k], zb = zp[k + 128];
            a1a = fmaf(za, ws[k*8 + h], a1a);
            a1c = fmaf(zb, ws[(k + 128)*8 + h], a1c);
            a2a = fmaf(za, ws[4096 + k*8 + h], a2a);
            a2c = fmaf(zb, ws[4096 + (k + 128)*8 + h], a2c);
        }
        g_A1[(r0 + row)*8 + h] = a1a + a1c;
        g_A2[(r0 + row)*8 + h] = a2a + a2c;
    } else if (blockIdx.x == 0 && tid < 160) {
        int t = tid - 128;
        int b = t >> 3, h = t & 7;
        float acc = ag_b[h];
        #pragma unroll 8
        for (int k = 0; k < 128; ++k)
            acc = fmaf(graph[b*128 + k], ag_w[k*8 + h], acc);
        g_ATTG[t] = acc;
    }
}

// =====================================================================
// Kernel C: fused attention, software-pipelined.
// Edge rows for tile t+1 prefetched into registers during tile t.
// vals/adj/att2 LDGs issued at sync1, STS deferred past phase A.
// =====================================================================
__global__ __launch_bounds__(256, 2) void gat_attn(
    const float* __restrict__ edge, const int* __restrict__ adj,
    const float* __restrict__ ae_w, const float* __restrict__ ae_b,
    float* __restrict__ out)
{
    __shared__ float atte2_s[NH*544];      // [h][ip][j(34)][io]
    __shared__ float vals_s[NH*640];       // [h][j*20 + d]
    __shared__ float adj2_s[8*68];         // [ip][j(34)][io]
    __shared__ ull   att2d_s[NH*36];       // [h][j] duplicated pairs
    __shared__ ulonglong2 w2s2[32];        // [d][hp01 | hp23]

    const int tid  = threadIdx.x;
    const int b    = blockIdx.x >> 6;
    const int it   = blockIdx.x & 63;
    const int i0   = it * TI;
    const int h    = tid >> 5;
    const int lane = tid & 31;
    const int ip   = lane >> 2;
    const int jq   = lane & 3;

    if (tid < 64) ((ull*)w2s2)[tid] = ((const ull*)ae_w)[tid];

    ull base2;
    {
        float gh = g_ATTG[b*8 + h] + ae_b[h];
        float b0 = g_A1[(b*NN + i0 + 2*ip)*8 + h] + gh;
        float b1 = g_A1[(b*NN + i0 + 2*ip + 1)*8 + h] + gh;
        base2 = pack2(b0, b1);
    }

    const float CAf = 0.505f * 1.4426950408889634f;
    const float CBf = 0.495f * 1.4426950408889634f;
    const ull CA2    = pack2(CAf, CAf);
    const ull CB2    = pack2(CBf, CBf);
    const ull MAGIC2 = pack2(12582912.0f, 12582912.0f);
    const ull NMAG2  = pack2(-12582912.0f, -12582912.0f);
    const ull MONE2  = pack2(-1.0f, -1.0f);
    const ull P4     = pack2(0.0096181291f, 0.0096181291f);
    const ull P3     = pack2(0.0555041087f, 0.0555041087f);
    const ull P2     = pack2(0.2402265070f, 0.2402265070f);
    const ull P1     = pack2(0.6931471806f, 0.6931471806f);
    const ull ONE2   = pack2(1.0f, 1.0f);

    ull acc0[8], acc1[8];
    #pragma unroll
    for (int q = 0; q < 8; ++q) { acc0[q] = 0ull; acc1[q] = 0ull; }
    ull s2 = 0ull;

    // per-thread fixed ids for staging / phase A
    const int pa_j  = tid & 31;
    const int st_d4 = tid & 3;
    const int st_j  = (tid >> 2) & 31;
    const int st_h0 = tid >> 7;            // 0 or 1
    const int a2_j  = tid >> 3;
    const int a2_h  = tid & 7;

    // prologue: prefetch edge tile 0 into registers
    float4 epre[2][4];
    #pragma unroll
    for (int pp = 0; pp < 2; ++pp) {
        int i = (pp << 3) + (tid >> 5);
        const float4* ep =
            (const float4*)&edge[(size_t)((b*NN + i0 + i)*NN + pa_j) * 16];
        epre[pp][0] = __ldcs(ep + 0);
        epre[pp][1] = __ldcs(ep + 1);
        epre[pp][2] = __ldcs(ep + 2);
        epre[pp][3] = __ldcs(ep + 3);
    }

    for (int j0g = 0; j0g < NN; j0g += TJ) {
        __syncthreads();   // B(t-1) done; smem free for overwrite

        // issue staging loads (latency hidden under phase A)
        float4 v4[4];
        #pragma unroll
        for (int c = 0; c < 4; ++c) {
            int hh = st_h0 + 2*c;
            v4[c] = *(const float4*)&g_V[(b*NN + j0g + st_j)*128 + hh*16 + st_d4*4];
        }
        float adj0 = (float)adj[(b*NN + i0 + 2*(tid >> 5))*NN + j0g + pa_j];
        float adj1 = (float)adj[(b*NN + i0 + 2*(tid >> 5) + 1)*NN + j0g + pa_j];
        float a2v  = g_A2[(b*NN + j0g + a2_j)*8 + a2_h];

        // phase A: compute att_e for both (i,j) tasks from prefetched regs
        #pragma unroll
        for (int pp = 0; pp < 2; ++pp) {
            int i = (pp << 3) + (tid >> 5);
            float4 e0 = epre[pp][0], e1 = epre[pp][1];
            float4 e2 = epre[pp][2], e3 = epre[pp][3];
            ull a0 = 0ull, a1 = 0ull, a2 = 0ull, a3 = 0ull;
            #define PA_STEP(dd, ev) { \
                ull ee = pack2(ev, ev); \
                ulonglong2 wA = w2s2[(dd)*2]; \
                ulonglong2 wB = w2s2[(dd)*2 + 1]; \
                a0 = ffma2(ee, wA.x, a0); a1 = ffma2(ee, wA.y, a1); \
                a2 = ffma2(ee, wB.x, a2); a3 = ffma2(ee, wB.y, a3); }
            PA_STEP(0,  e0.x) PA_STEP(1,  e0.y) PA_STEP(2,  e0.z) PA_STEP(3,  e0.w)
            PA_STEP(4,  e1.x) PA_STEP(5,  e1.y) PA_STEP(6,  e1.z) PA_STEP(7,  e1.w)
            PA_STEP(8,  e2.x) PA_STEP(9,  e2.y) PA_STEP(10, e2.z) PA_STEP(11, e2.w)
            PA_STEP(12, e3.x) PA_STEP(13, e3.y) PA_STEP(14, e3.z) PA_STEP(15, e3.w)
            #undef PA_STEP
            int bidx = ((i >> 1)*34 + pa_j)*2 + (i & 1);
            float2 f0 = unpack2(a0), f1 = unpack2(a1);
            float2 f2 = unpack2(a2), f3 = unpack2(a3);
            atte2_s[0*544 + bidx] = f0.x;
            atte2_s[1*544 + bidx] = f0.y;
            atte2_s[2*544 + bidx] = f1.x;
            atte2_s[3*544 + bidx] = f1.y;
            atte2_s[4*544 + bidx] = f2.x;
            atte2_s[5*544 + bidx] = f2.y;
            atte2_s[6*544 + bidx] = f3.x;
            atte2_s[7*544 + bidx] = f3.y;
        }

        // prefetch next tile's edge rows (in flight across phase B)
        if (j0g + TJ < NN) {
            #pragma unroll
            for (int pp = 0; pp < 2; ++pp) {
                int i = (pp << 3) + (tid >> 5);
                const float4* ep = (const float4*)
                    &edge[(size_t)((b*NN + i0 + i)*NN + j0g + TJ + pa_j) * 16];
                epre[pp][0] = __ldcs(ep + 0);
                epre[pp][1] = __ldcs(ep + 1);
                epre[pp][2] = __ldcs(ep + 2);
                epre[pp][3] = __ldcs(ep + 3);
            }
        }

        // deferred STS of staged data
        #pragma unroll
        for (int c = 0; c < 4; ++c) {
            int hh = st_h0 + 2*c;
            *(float4*)&vals_s[hh*640 + st_j*20 + st_d4*4] = v4[c];
        }
        {
            float2 am; am.x = adj0; am.y = adj1;
            *(float2*)&adj2_s[((tid >> 5)*34 + pa_j)*2] = am;
        }
        att2d_s[a2_h*36 + a2_j] = pack2(a2v, a2v);

        __syncthreads();   // sync2: atte/vals/adj/att2 published

        // phase B
        const float* ap  = &atte2_s[h*544 + ip*68];
        const float* vp  = &vals_s[h*640];
        const ull*   a2p = &att2d_s[h*36];
        const float* adp = &adj2_s[ip*68];
        #pragma unroll
        for (int jj = 0; jj < 8; ++jj) {
            int j = jj*4 + jq;
            ull x2 = *(const ull*)&ap[j*2];
            x2 = fadd2(x2, base2);
            x2 = fadd2(x2, a2p[j]);
            ull ax = x2 & 0x7fffffff7fffffffULL;
            ull tt = fmul2(x2, CA2);
            tt = ffma2(ax, CB2, tt);
            ull r2 = fadd2(tt, MAGIC2);
            ull rm = fadd2(r2, NMAG2);
            ull f2 = ffma2(rm, MONE2, tt);
            unsigned rl = (unsigned)r2, rh = (unsigned)(r2 >> 32);
            float sl = __int_as_float((int)((rl - 0x4B3FFF81u) << 23));
            float sh = __int_as_float((int)((rh - 0x4B3FFF81u) << 23));
            ull p2 = ffma2(P4, f2, P3);
            p2 = ffma2(p2, f2, P2);
            p2 = ffma2(p2, f2, P1);
            p2 = ffma2(p2, f2, ONE2);
            p2 = fmul2(p2, pack2(sl, sh));
            p2 = fmul2(p2, *(const ull*)&adp[j*2]);
            s2 = fadd2(s2, p2);
            float2 pf = unpack2(p2);
            ull pp0 = pack2(pf.x, pf.x);
            ull pp1 = pack2(pf.y, pf.y);
            ulonglong2 va = *(const ulonglong2*)&vp[j*20];
            ulonglong2 vb = *(const ulonglong2*)&vp[j*20 + 4];
            ulonglong2 vc = *(const ulonglong2*)&vp[j*20 + 8];
            ulonglong2 vd = *(const ulonglong2*)&vp[j*20 + 12];
            acc0[0]=ffma2(pp0,va.x,acc0[0]); acc0[1]=ffma2(pp0,va.y,acc0[1]);
            acc0[2]=ffma2(pp0,vb.x,acc0[2]); acc0[3]=ffma2(pp0,vb.y,acc0[3]);
            acc0[4]=ffma2(pp0,vc.x,acc0[4]); acc0[5]=ffma2(pp0,vc.y,acc0[5]);
            acc0[6]=ffma2(pp0,vd.x,acc0[6]); acc0[7]=ffma2(pp0,vd.y,acc0[7]);
            acc1[0]=ffma2(pp1,va.x,acc1[0]); acc1[1]=ffma2(pp1,va.y,acc1[1]);
            acc1[2]=ffma2(pp1,vb.x,acc1[2]); acc1[3]=ffma2(pp1,vb.y,acc1[3]);
            acc1[4]=ffma2(pp1,vc.x,acc1[4]); acc1[5]=ffma2(pp1,vc.y,acc1[5]);
            acc1[6]=ffma2(pp1,vd.x,acc1[6]); acc1[7]=ffma2(pp1,vd.y,acc1[7]);
        }
    }

    // reduce across j-quarters (lane bits 0-1)
    #pragma unroll
    for (int m = 1; m <= 2; m <<= 1) {
        #pragma unroll
        for (int q = 0; q < 8; ++q) {
            acc0[q] = fadd2(acc0[q], shflx2(acc0[q], m));
            acc1[q] = fadd2(acc1[q], shflx2(acc1[q], m));
        }
        s2 = fadd2(s2, shflx2(s2, m));
    }
    if (jq == 0) {
        float2 sf = unpack2(s2);
        float inv0 = 1.0f / sf.x;
        float inv1 = 1.0f / sf.y;
        int r0o = (b*NN + i0 + 2*ip)*128 + h*16;
        #pragma unroll
        for (int q4 = 0; q4 < 4; ++q4) {
            float4 sk = *(const float4*)&g_SKIP[r0o + q4*4];
            float2 u0 = unpack2(acc0[q4*2]), u1 = unpack2(acc0[q4*2 + 1]);
            float4 o;
            o.x = fmaxf(fmaf(u0.x, inv0, sk.x), 0.0f);
            o.y = fmaxf(fmaf(u0.y, inv0, sk.y), 0.0f);
            o.z = fmaxf(fmaf(u1.x, inv0, sk.z), 0.0f);
            o.w = fmaxf(fmaf(u1.y, inv0, sk.w), 0.0f);
            *(float4*)&out[r0o + q4*4] = o;
        }
        int r1o = r0o + 128;
        #pragma unroll
        for (int q4 = 0; q4 < 4; ++q4) {
            float4 sk = *(const float4*)&g_SKIP[r1o + q4*4];
            float2 u0 = unpack2(acc1[q4*2]), u1 = unpack2(acc1[q4*2 + 1]);
            float4 o;
            o.x = fmaxf(fmaf(u0.x, inv1, sk.x), 0.0f);
            o.y = fmaxf(fmaf(u0.y, inv1, sk.y), 0.0f);
            o.z = fmaxf(fmaf(u1.x, inv1, sk.z), 0.0f);
            o.w = fmaxf(fmaf(u1.y, inv1, sk.w), 0.0f);
            *(float4*)&out[r1o + q4*4] = o;
        }
    }
}

// =====================================================================
extern "C" void kernel_launch(void* const* d_in, const int* in_sizes, int n_in,
                              void* d_out, int out_size)
{
    const float* node   = (const float*)d_in[0];
    const float* edge   = (const float*)d_in[1];
    const float* graph  = (const float*)d_in[2];
    const int*   adj    = (const int*)  d_in[3];
    const float* hidden = (const float*)d_in[4];
    const float* m_w    = (const float*)d_in[5];
    const float* m_b    = (const float*)d_in[6];
    const float* skip_w = (const float*)d_in[7];
    const float* skip_b = (const float*)d_in[8];
    const float* a1_w   = (const float*)d_in[9];
    const float* a1_b   = (const float*)d_in[10];
    const float* a2_w   = (const float*)d_in[11];
    const float* a2_b   = (const float*)d_in[12];
    const float* ae_w   = (const float*)d_in[13];
    const float* ae_b   = (const float*)d_in[14];
    const float* ag_w   = (const float*)d_in[15];
    const float* ag_b   = (const float*)d_in[16];
    float* out = (float*)d_out;

    const int prep_smem = (16*ZSTR + 8192) * 4;   // 49408 B
    cudaFuncSetAttribute(gat_prep, cudaFuncAttributeMaxDynamicSharedMemorySize,
                         prep_smem);

    gat_prep<<<BN/16, 256, prep_smem>>>(node, hidden, m_w, m_b, skip_w, skip_b,
                                        a1_w, a1_b, a2_w, a2_b,
                                        graph, ag_w, ag_b);
    gat_attn<<<4 * (NN/TI), 256>>>(edge, adj, ae_w, ae_b, out);
}

// round 5
// speedup vs baseline: 1.2539x; 1.2539x over previous
#include <cuda_runtime.h>

#define NN 1024
#define BN 4096
#define NH 8
#define TI 16
#define TJ 32

typedef unsigned long long ull;

// ---- scratch ----
__device__ float g_V[BN*128];
__device__ float g_SKIP[BN*128];
__device__ float g_A1[BN*NH];
__device__ float g_A2[BN*NH];
__device__ float g_ATTG[4*NH];

// ---- packed f32x2 helpers ----
__device__ __forceinline__ ull ffma2(ull a, ull b, ull c) {
    ull d; asm("fma.rn.f32x2 %0,%1,%2,%3;" : "=l"(d) : "l"(a), "l"(b), "l"(c)); return d;
}
__device__ __forceinline__ ull fadd2(ull a, ull b) {
    ull d; asm("add.rn.f32x2 %0,%1,%2;" : "=l"(d) : "l"(a), "l"(b)); return d;
}
__device__ __forceinline__ ull fmul2(ull a, ull b) {
    ull d; asm("mul.rn.f32x2 %0,%1,%2;" : "=l"(d) : "l"(a), "l"(b)); return d;
}
__device__ __forceinline__ ull pack2(float x, float y) {
    ull r; asm("mov.b64 %0,{%1,%2};" : "=l"(r) : "f"(x), "f"(y)); return r;
}
__device__ __forceinline__ float2 unpack2(ull v) {
    float2 r; asm("mov.b64 {%0,%1},%2;" : "=f"(r.x), "=f"(r.y) : "l"(v)); return r;
}
__device__ __forceinline__ ull shflx2(ull v, int m) {
    unsigned lo = (unsigned)v, hi = (unsigned)(v >> 32);
    lo = __shfl_xor_sync(0xffffffffu, lo, m);
    hi = __shfl_xor_sync(0xffffffffu, hi, m);
    return ((ull)hi << 32) | (ull)lo;
}

// =====================================================================
// Kernel A: per-node GEMMs (unchanged from R4: 16 rows/block, 3 blk/SM).
// =====================================================================
#define ZSTR 260
__global__ __launch_bounds__(256, 3) void gat_prep(
    const float* __restrict__ node, const float* __restrict__ hidden,
    const float* __restrict__ m_w,  const float* __restrict__ m_b,
    const float* __restrict__ skip_w, const float* __restrict__ skip_b,
    const float* __restrict__ a1_w, const float* __restrict__ a1_b,
    const float* __restrict__ a2_w, const float* __restrict__ a2_b,
    const float* __restrict__ graph, const float* __restrict__ ag_w,
    const float* __restrict__ ag_b)
{
    extern __shared__ float sm[];
    float* zs = sm;
    float* ws = sm + 16*ZSTR;

    const int tid = threadIdx.x;
    const int r0  = blockIdx.x * 16;

    for (int t = tid; t < 16*64; t += 256) {
        int r = t >> 6, q = t & 63;
        float4 v = (q < 32) ? ((const float4*)node)[(r0 + r)*32 + q]
                            : ((const float4*)hidden)[(r0 + r)*32 + (q - 32)];
        *(float4*)&zs[r*ZSTR + q*4] = v;
    }

    const int cg = tid & 31;
    const int rg = tid >> 5;
    const int c0 = cg * 4;
    const int rowb = rg * 2;

    ull av[2][2], ak[2][2];
    {
        ulonglong2 bv = *(const ulonglong2*)&m_b[c0];
        ulonglong2 bk = *(const ulonglong2*)&skip_b[c0];
        #pragma unroll
        for (int rr = 0; rr < 2; ++rr) {
            av[rr][0] = bv.x; av[rr][1] = bv.y;
            ak[rr][0] = bk.x; ak[rr][1] = bk.y;
        }
    }

    for (int kk = 0; kk < 256; kk += 32) {
        __syncthreads();
        for (int t = tid; t < 2048; t += 256) {
            float4 v = (t < 1024) ? ((const float4*)m_w)[kk*32 + t]
                                  : ((const float4*)skip_w)[kk*32 + (t - 1024)];
            ((float4*)ws)[t] = v;
        }
        __syncthreads();
        #pragma unroll
        for (int k = 0; k < 32; ++k) {
            ulonglong2 wv = *(const ulonglong2*)&ws[k*128 + c0];
            ulonglong2 wk = *(const ulonglong2*)&ws[4096 + k*128 + c0];
            #pragma unroll
            for (int rr = 0; rr < 2; ++rr) {
                float z = zs[(rowb + rr)*ZSTR + kk + k];
                ull zz = pack2(z, z);
                av[rr][0] = ffma2(zz, wv.x, av[rr][0]);
                av[rr][1] = ffma2(zz, wv.y, av[rr][1]);
                ak[rr][0] = ffma2(zz, wk.x, ak[rr][0]);
                ak[rr][1] = ffma2(zz, wk.y, ak[rr][1]);
            }
        }
    }
    #pragma unroll
    for (int rr = 0; rr < 2; ++rr) {
        int rowg = r0 + rowb + rr;
        ulonglong2 o;
        o.x = av[rr][0]; o.y = av[rr][1];
        *(ulonglong2*)&g_V[rowg*128 + c0] = o;
        o.x = ak[rr][0]; o.y = ak[rr][1];
        *(ulonglong2*)&g_SKIP[rowg*128 + c0] = o;
    }

    __syncthreads();
    for (int t = tid; t < 2048; t += 256) {
        ws[t] = a1_w[t];
        ws[4096 + t] = a2_w[t];
    }
    __syncthreads();
    if (tid < 128) {
        int row = tid >> 3, h = tid & 7;
        float a1a = a1_b[h], a1c = 0.0f, a2a = a2_b[h], a2c = 0.0f;
        const float* zp = &zs[row*ZSTR];
        #pragma unroll 8
        for (int k = 0; k < 128; ++k) {
            float za = zp[k], zb = zp[k + 128];
            a1a = fmaf(za, ws[k*8 + h], a1a);
            a1c = fmaf(zb, ws[(k + 128)*8 + h], a1c);
            a2a = fmaf(za, ws[4096 + k*8 + h], a2a);
            a2c = fmaf(zb, ws[4096 + (k + 128)*8 + h], a2c);
        }
        g_A1[(r0 + row)*8 + h] = a1a + a1c;
        g_A2[(r0 + row)*8 + h] = a2a + a2c;
    } else if (blockIdx.x == 0 && tid < 160) {
        int t = tid - 128;
        int b = t >> 3, h = t & 7;
        float acc = ag_b[h];
        #pragma unroll 8
        for (int k = 0; k < 128; ++k)
            acc = fmaf(graph[b*128 + k], ag_w[k*8 + h], acc);
        g_ATTG[t] = acc;
    }
}

// =====================================================================
// Kernel C: fused attention, register-resident ae_w.
// Phase A unit = (i, j, head-pair): 4 hp-lanes dedup one edge row;
//   computes full masked/leaky/log2-scaled logit t and stores scalars.
// Phase B: exp2 on i-pair packed t + p·v accumulation. No weight LDS.
// t_s layout [h][ip][io][j]: strides 612/76/36/1 -> conflict-free.
// =====================================================================
__global__ __launch_bounds__(256, 2) void gat_attn(
    const float* __restrict__ edge, const int* __restrict__ adj,
    const float* __restrict__ ae_w, const float* __restrict__ ae_b,
    float* __restrict__ out)
{
    __shared__ float t_s[NH*612];     // 19.6KB
    __shared__ float vals_s[NH*640];  // 20.5KB
    __shared__ ull   base_s[64];      // [i][hp]

    const int tid  = threadIdx.x;
    const int b    = blockIdx.x >> 6;
    const int it   = blockIdx.x & 63;
    const int i0   = it * TI;
    const int w    = tid >> 5;
    const int lane = tid & 31;
    // phase A ids
    const int hp = lane & 3;
    const int t3 = lane >> 2;
    // phase B ids
    const int h  = w;
    const int ip = lane >> 2;
    const int jq = lane & 3;

    // ae_w resident in registers (d-pair packed, per head of this lane's pair)
    ull wh0[8], wh1[8];
    #pragma unroll
    for (int q = 0; q < 8; ++q) {
        wh0[q] = pack2(ae_w[(2*q)*8 + 2*hp],     ae_w[(2*q+1)*8 + 2*hp]);
        wh1[q] = pack2(ae_w[(2*q)*8 + 2*hp + 1], ae_w[(2*q+1)*8 + 2*hp + 1]);
    }

    // block-constant base table: base_s[i*4+hp] = (a1+attg+aeb) for (h0,h1)
    if (tid < 64) {
        int ib = tid >> 2, hpb = tid & 3;
        float g0 = g_ATTG[b*8 + 2*hpb]     + ae_b[2*hpb];
        float g1 = g_ATTG[b*8 + 2*hpb + 1] + ae_b[2*hpb + 1];
        base_s[tid] = pack2(g_A1[(b*NN + i0 + ib)*8 + 2*hpb] + g0,
                            g_A1[(b*NN + i0 + ib)*8 + 2*hpb + 1] + g1);
    }
    __syncthreads();

    const float CAf = 0.505f * 1.4426950408889634f;
    const float CBf = 0.495f * 1.4426950408889634f;
    const ull CA2    = pack2(CAf, CAf);
    const ull CB2    = pack2(CBf, CBf);
    const ull NEG60  = pack2(-60.0f, -60.0f);
    const ull MAGIC2 = pack2(12582912.0f, 12582912.0f);
    const ull NMAG2  = pack2(-12582912.0f, -12582912.0f);
    const ull MONE2  = pack2(-1.0f, -1.0f);
    const ull P4     = pack2(0.0096181291f, 0.0096181291f);
    const ull P3     = pack2(0.0555041087f, 0.0555041087f);
    const ull P2     = pack2(0.2402265070f, 0.2402265070f);
    const ull P1     = pack2(0.6931471806f, 0.6931471806f);
    const ull ONE2   = pack2(1.0f, 1.0f);

    ull acc0[8], acc1[8];
    #pragma unroll
    for (int q = 0; q < 8; ++q) { acc0[q] = 0ull; acc1[q] = 0ull; }
    ull s2 = 0ull;

    // vals staging ids
    const int st_d4 = tid & 3;
    const int st_j  = (tid >> 2) & 31;
    const int st_h0 = tid >> 7;

    for (int j0g = 0; j0g < NN; j0g += TJ) {
        __syncthreads();   // phase B of previous tile done

        // vals staging loads (latency hidden under phase A)
        float4 v4[4];
        #pragma unroll
        for (int c = 0; c < 4; ++c) {
            int hh = st_h0 + 2*c;
            v4[c] = *(const float4*)&g_V[(b*NN + j0g + st_j)*128 + hh*16 + st_d4*4];
        }

        // ---- phase A ----
        #pragma unroll
        for (int pp = 0; pp < 2; ++pp) {
            const int i = pp*8 + w;
            const float* erow = edge + ((size_t)(b*NN + i0 + i))*NN*16 + (size_t)j0g*16;
            const int*   arow = adj + (size_t)(b*NN + i0 + i)*NN + j0g;
            const ull bse = base_s[i*4 + hp];
            const int tb0 = (2*hp)*612 + (i >> 1)*76 + (i & 1)*36;

            ulonglong2 eb[2][4];
            int  adjb[2];
            ull  a2b[2];
            {
                const ulonglong2* ep = (const ulonglong2*)(erow + (size_t)t3*16);
                eb[0][0] = __ldcs(ep + 0); eb[0][1] = __ldcs(ep + 1);
                eb[0][2] = __ldcs(ep + 2); eb[0][3] = __ldcs(ep + 3);
                adjb[0]  = arow[t3];
                a2b[0]   = *(const ull*)&g_A2[(size_t)(b*NN + j0g + t3)*8 + 2*hp];
            }
            #pragma unroll
            for (int jo = 0; jo < 4; ++jo) {
                const int cur = jo & 1, nxt = cur ^ 1;
                if (jo < 3) {
                    int jn = (jo + 1)*8 + t3;
                    const ulonglong2* ep = (const ulonglong2*)(erow + (size_t)jn*16);
                    eb[nxt][0] = __ldcs(ep + 0); eb[nxt][1] = __ldcs(ep + 1);
                    eb[nxt][2] = __ldcs(ep + 2); eb[nxt][3] = __ldcs(ep + 3);
                    adjb[nxt]  = arow[jn];
                    a2b[nxt]   = *(const ull*)&g_A2[(size_t)(b*NN + j0g + jn)*8 + 2*hp];
                }
                const int j = jo*8 + t3;
                ulonglong2 ea = eb[cur][0], eb_ = eb[cur][1];
                ulonglong2 ec = eb[cur][2], ed = eb[cur][3];
                ull aA = ffma2(ea.x, wh0[0], 0ull);
                ull aB = ffma2(ea.x, wh1[0], 0ull);
                aA = ffma2(ea.y, wh0[1], aA);  aB = ffma2(ea.y, wh1[1], aB);
                aA = ffma2(eb_.x, wh0[2], aA); aB = ffma2(eb_.x, wh1[2], aB);
                aA = ffma2(eb_.y, wh0[3], aA); aB = ffma2(eb_.y, wh1[3], aB);
                aA = ffma2(ec.x, wh0[4], aA);  aB = ffma2(ec.x, wh1[4], aB);
                aA = ffma2(ec.y, wh0[5], aA);  aB = ffma2(ec.y, wh1[5], aB);
                aA = ffma2(ed.x, wh0[6], aA);  aB = ffma2(ed.x, wh1[6], aB);
                aA = ffma2(ed.y, wh0[7], aA);  aB = ffma2(ed.y, wh1[7], aB);
                float2 fA = unpack2(aA), fB = unpack2(aB);
                ull t2 = pack2(fA.x + fA.y, fB.x + fB.y);
                t2 = fadd2(t2, bse);
                t2 = fadd2(t2, a2b[cur]);
                ull ax = t2 & 0x7fffffff7fffffffULL;
                ull l2 = fmul2(t2, CA2);
                l2 = ffma2(ax, CB2, l2);
                l2 = adjb[cur] ? l2 : NEG60;
                float2 lf = unpack2(l2);
                t_s[tb0 + j]       = lf.x;
                t_s[tb0 + 612 + j] = lf.y;
            }
        }

        // deferred vals STS
        #pragma unroll
        for (int c = 0; c < 4; ++c) {
            int hh = st_h0 + 2*c;
            *(float4*)&vals_s[hh*640 + st_j*20 + st_d4*4] = v4[c];
        }

        __syncthreads();   // t_s / vals published

        // ---- phase B ----
        const float* tp = &t_s[h*612 + ip*76];
        const float* vp = &vals_s[h*640];
        #pragma unroll
        for (int jj = 0; jj < 8; ++jj) {
            const int j = jj*4 + jq;
            ull x2 = pack2(tp[j], tp[36 + j]);
            ull r2 = fadd2(x2, MAGIC2);
            ull rm = fadd2(r2, NMAG2);
            ull f2 = ffma2(rm, MONE2, x2);
            unsigned rl = (unsigned)r2, rh = (unsigned)(r2 >> 32);
            float sl = __int_as_float((int)((rl - 0x4B3FFF81u) << 23));
            float sh = __int_as_float((int)((rh - 0x4B3FFF81u) << 23));
            ull p2 = ffma2(P4, f2, P3);
            p2 = ffma2(p2, f2, P2);
            p2 = ffma2(p2, f2, P1);
            p2 = ffma2(p2, f2, ONE2);
            p2 = fmul2(p2, pack2(sl, sh));
            s2 = fadd2(s2, p2);
            float2 pf = unpack2(p2);
            ull pp0 = pack2(pf.x, pf.x);
            ull pp1 = pack2(pf.y, pf.y);
            ulonglong2 va = *(const ulonglong2*)&vp[j*20];
            ulonglong2 vb = *(const ulonglong2*)&vp[j*20 + 4];
            ulonglong2 vc = *(const ulonglong2*)&vp[j*20 + 8];
            ulonglong2 vd = *(const ulonglong2*)&vp[j*20 + 12];
            acc0[0]=ffma2(pp0,va.x,acc0[0]); acc0[1]=ffma2(pp0,va.y,acc0[1]);
            acc0[2]=ffma2(pp0,vb.x,acc0[2]); acc0[3]=ffma2(pp0,vb.y,acc0[3]);
            acc0[4]=ffma2(pp0,vc.x,acc0[4]); acc0[5]=ffma2(pp0,vc.y,acc0[5]);
            acc0[6]=ffma2(pp0,vd.x,acc0[6]); acc0[7]=ffma2(pp0,vd.y,acc0[7]);
            acc1[0]=ffma2(pp1,va.x,acc1[0]); acc1[1]=ffma2(pp1,va.y,acc1[1]);
            acc1[2]=ffma2(pp1,vb.x,acc1[2]); acc1[3]=ffma2(pp1,vb.y,acc1[3]);
            acc1[4]=ffma2(pp1,vc.x,acc1[4]); acc1[5]=ffma2(pp1,vc.y,acc1[5]);
            acc1[6]=ffma2(pp1,vd.x,acc1[6]); acc1[7]=ffma2(pp1,vd.y,acc1[7]);
        }
    }

    // reduce across j-quarters (lane bits 0-1)
    #pragma unroll
    for (int m = 1; m <= 2; m <<= 1) {
        #pragma unroll
        for (int q = 0; q < 8; ++q) {
            acc0[q] = fadd2(acc0[q], shflx2(acc0[q], m));
            acc1[q] = fadd2(acc1[q], shflx2(acc1[q], m));
        }
        s2 = fadd2(s2, shflx2(s2, m));
    }
    if (jq == 0) {
        float2 sf = unpack2(s2);
        float inv0 = 1.0f / sf.x;
        float inv1 = 1.0f / sf.y;
        int r0o = (b*NN + i0 + 2*ip)*128 + h*16;
        #pragma unroll
        for (int q4 = 0; q4 < 4; ++q4) {
            float4 sk = *(const float4*)&g_SKIP[r0o + q4*4];
            float2 u0 = unpack2(acc0[q4*2]), u1 = unpack2(acc0[q4*2 + 1]);
            float4 o;
            o.x = fmaxf(fmaf(u0.x, inv0, sk.x), 0.0f);
            o.y = fmaxf(fmaf(u0.y, inv0, sk.y), 0.0f);
            o.z = fmaxf(fmaf(u1.x, inv0, sk.z), 0.0f);
            o.w = fmaxf(fmaf(u1.y, inv0, sk.w), 0.0f);
            *(float4*)&out[r0o + q4*4] = o;
        }
        int r1o = r0o + 128;
        #pragma unroll
        for (int q4 = 0; q4 < 4; ++q4) {
            float4 sk = *(const float4*)&g_SKIP[r1o + q4*4];
            float2 u0 = unpack2(acc1[q4*2]), u1 = unpack2(acc1[q4*2 + 1]);
            float4 o;
            o.x = fmaxf(fmaf(u0.x, inv1, sk.x), 0.0f);
            o.y = fmaxf(fmaf(u0.y, inv1, sk.y), 0.0f);
            o.z = fmaxf(fmaf(u1.x, inv1, sk.z), 0.0f);
            o.w = fmaxf(fmaf(u1.y, inv1, sk.w), 0.0f);
            *(float4*)&out[r1o + q4*4] = o;
        }
    }
}

// =====================================================================
extern "C" void kernel_launch(void* const* d_in, const int* in_sizes, int n_in,
                              void* d_out, int out_size)
{
    const float* node   = (const float*)d_in[0];
    const float* edge   = (const float*)d_in[1];
    const float* graph  = (const float*)d_in[2];
    const int*   adj    = (const int*)  d_in[3];
    const float* hidden = (const float*)d_in[4];
    const float* m_w    = (const float*)d_in[5];
    const float* m_b    = (const float*)d_in[6];
    const float* skip_w = (const float*)d_in[7];
    const float* skip_b = (const float*)d_in[8];
    const float* a1_w   = (const float*)d_in[9];
    const float* a1_b   = (const float*)d_in[10];
    const float* a2_w   = (const float*)d_in[11];
    const float* a2_b   = (const float*)d_in[12];
    const float* ae_w   = (const float*)d_in[13];
    const float* ae_b   = (const float*)d_in[14];
    const float* ag_w   = (const float*)d_in[15];
    const float* ag_b   = (const float*)d_in[16];
    float* out = (float*)d_out;

    const int prep_smem = (16*ZSTR + 8192) * 4;   // 49408 B
    cudaFuncSetAttribute(gat_prep, cudaFuncAttributeMaxDynamicSharedMemorySize,
                         prep_smem);

    gat_prep<<<BN/16, 256, prep_smem>>>(node, hidden, m_w, m_b, skip_w, skip_b,
                                        a1_w, a1_b, a2_w, a2_b,
                                        graph, ag_w, ag_b);
    gat_attn<<<4 * (NN/TI), 256>>>(edge, adj, ae_w, ae_b, out);
}